// round 8
// baseline (speedup 1.0000x reference)
#include <cuda_runtime.h>
#include <cuda_bf16.h>
#include <cstdint>

// Spatially-varying 19x19 blur.
// out[b,c,i,j] = (1/361) * sum_{u,v} x_reflectpad[b,c,i+u-9,j+v-9] * kernel[b,u*19+v,i,j]
//
// R8: cp.async.bulk smem ring for the kernel tensor, HARDENED sync:
//  - no empty-mbarriers: __syncthreads() per chunk is the backpressure
//    (all threads consume every chunk, so buf (c-1)%NS is provably free)
//  - only wait is on 'full' barriers whose completion is HW-guaranteed.
// 128 thr/block, TI=2 full-width, NS=5 stages x 8KB, 256 blocks (2/SM).

#define LK    19
#define PADR  9
#define HGT   256
#define WID   256
#define HW    (HGT * WID)
#define K2    (LK * LK)

#define TI    2
#define NTHR  128
#define PCOLS (WID + LK - 1)     // 274
#define PROWS (TI + LK - 1)      // 20
#define PITCH 276                // 16B-aligned float4 rows

#define NS          5
#define NCHUNK      (LK * 5)                 // 95: (u, vb) pairs
#define TAP_BYTES   (TI * WID * 4)           // 2048
#define STAGE_BYTES (4 * TAP_BYTES)          // 8192
#define STAGE_F4    (STAGE_BYTES / 16)       // 512
#define TAP_F4      (TAP_BYTES / 16)         // 128

#define PATCH_FLOATS (3 * PROWS * PITCH)                       // 16560
#define SMEM_BYTES   (PATCH_FLOATS * 4 + NS * STAGE_BYTES)     // 107200

__device__ __forceinline__ uint32_t smem_u32(const void* p) {
    return (uint32_t)__cvta_generic_to_shared(p);
}
#define MBAR_INIT(a, n) \
    asm volatile("mbarrier.init.shared.b64 [%0], %1;" :: "r"(a), "r"(n) : "memory")
#define MBAR_EXPECT_TX(a, b) \
    asm volatile("mbarrier.arrive.expect_tx.shared.b64 _, [%0], %1;" :: "r"(a), "r"(b) : "memory")
#define MBAR_WAIT(a, ph) do {                                                  \
    asm volatile(                                                              \
        "{\n\t.reg .pred P;\n\t"                                               \
        "W%=:\n\t"                                                             \
        "mbarrier.try_wait.parity.acquire.cta.shared::cta.b64 P, [%0], %1, 0x989680;\n\t" \
        "@P bra.uni D%=;\n\t"                                                  \
        "bra.uni W%=;\n\t"                                                     \
        "D%=:\n\t}"                                                            \
        :: "r"(a), "r"(ph) : "memory");                                        \
} while (0)
#define BULK_CP(dst, src, bytes, mbar) \
    asm volatile("cp.async.bulk.shared::cta.global.mbarrier::complete_tx::bytes " \
                 "[%0], [%1], %2, [%3];" \
                 :: "r"(dst), "l"(src), "r"(bytes), "r"(mbar) : "memory")

__global__ __launch_bounds__(NTHR)
void svblur_kernel(const float* __restrict__ x,
                   const float* __restrict__ kern,
                   float* __restrict__ out)
{
    extern __shared__ float dsm[];
    float* patch = dsm;                       // [3][PROWS][PITCH]
    float* stg   = dsm + PATCH_FLOATS;        // [NS][2048 floats]
    __shared__ uint64_t mbar[NS];             // full barriers

    const int tid = threadIdx.x;
    const int ip  = blockIdx.x;      // 0..127
    const int b   = blockIdx.y;      // 0..1
    const int i0  = ip * TI;

    const uint32_t full0 = smem_u32(&mbar[0]);
    const uint32_t stg0  = smem_u32(stg);

    if (tid == 0) {
        #pragma unroll
        for (int s = 0; s < NS; s++) MBAR_INIT(full0 + s * 8, 1);
    }

    // ---- stage input patch (reflect padding), all 3 channels ----
    const float* xb = x + (size_t)b * 3 * HW;
    for (int e = tid; e < PROWS * PCOLS; e += NTHR) {
        int pr = e / PCOLS;
        int pc = e - pr * PCOLS;
        int gi = i0 - PADR + pr;
        int gj = -PADR + pc;
        gi = (gi < 0) ? -gi : ((gi >= HGT) ? 2 * (HGT - 1) - gi : gi);
        gj = (gj < 0) ? -gj : ((gj >= WID) ? 2 * (WID - 1) - gj : gj);
        const float* src = xb + gi * WID + gj;
        patch[(0 * PROWS + pr) * PITCH + pc] = src[0 * HW];
        patch[(1 * PROWS + pr) * PITCH + pc] = src[1 * HW];
        patch[(2 * PROWS + pr) * PITCH + pc] = src[2 * HW];
    }
    __syncthreads();   // mbarrier init + patch visible to all

    const int jthr = tid & 63;        // 0..63 : float4 column
    const int ir   = tid >> 6;        // 0..1  : row within pair
    const int jj   = jthr * 4;

    const float* kbase = kern + (size_t)b * K2 * HW + (size_t)i0 * WID;

    // issue chunk 'pc' into slot pc%NS (2KB bulk per tap, <=4 taps)
    auto issue = [&](int pc) {
        const int u    = pc / 5;
        const int vb   = pc % 5;
        const int vmax = (vb == 4) ? 3 : 4;
        const int kb   = u * LK + vb * 4;
        const int slot = pc % NS;
        const uint32_t fb  = full0 + slot * 8;
        const uint32_t dst = stg0 + slot * STAGE_BYTES;
        MBAR_EXPECT_TX(fb, vmax * TAP_BYTES);
        #pragma unroll
        for (int t = 0; t < 4; t++) {
            if (t >= vmax) break;
            BULK_CP(dst + t * TAP_BYTES, kbase + (size_t)(kb + t) * HW,
                    TAP_BYTES, fb);
        }
    };

    if (tid == 0) {
        for (int pc = 0; pc < NS - 1; pc++) issue(pc);   // prefill slots 0..3
    }

    float a0[4] = {0.f, 0.f, 0.f, 0.f};
    float a1[4] = {0.f, 0.f, 0.f, 0.f};
    float a2[4] = {0.f, 0.f, 0.f, 0.f};

    int c = 0;   // chunk counter
    #pragma unroll 1
    for (int u = 0; u < LK; u++) {
        const float4* r0 = (const float4*)&patch[(0 * PROWS + ir + u) * PITCH];
        const float4* r1 = (const float4*)&patch[(1 * PROWS + ir + u) * PITCH];
        const float4* r2 = (const float4*)&patch[(2 * PROWS + ir + u) * PITCH];
        // sliding float4 carry across vb chunks (halves window LDS traffic)
        float4 p0 = r0[jthr], p1 = r1[jthr], p2 = r2[jthr];

        #pragma unroll
        for (int vb = 0; vb < 5; vb++, c++) {
            // backpressure: everyone is done with slot (c-1)%NS after this
            __syncthreads();
            if (tid == 0 && c + NS - 1 < NCHUNK) issue(c + NS - 1);

            const int slot = c % NS;
            MBAR_WAIT(full0 + slot * 8, (c / NS) & 1);

            const int vmax = (vb == 4) ? 3 : 4;
            float4 h0 = r0[jthr + vb + 1];
            float4 h1 = r1[jthr + vb + 1];
            float4 h2 = r2[jthr + vb + 1];
            float w0[8] = {p0.x, p0.y, p0.z, p0.w, h0.x, h0.y, h0.z, h0.w};
            float w1[8] = {p1.x, p1.y, p1.z, p1.w, h1.x, h1.y, h1.z, h1.w};
            float w2[8] = {p2.x, p2.y, p2.z, p2.w, h2.x, h2.y, h2.z, h2.w};

            const float4* kvs = (const float4*)(stg) + slot * STAGE_F4
                                + ir * (TAP_F4 / 2) + jthr;
            #pragma unroll
            for (int s = 0; s < 4; s++) {
                if (s >= vmax) break;
                float4 kv = kvs[s * TAP_F4];
                a0[0] += w0[s + 0] * kv.x;  a0[1] += w0[s + 1] * kv.y;
                a0[2] += w0[s + 2] * kv.z;  a0[3] += w0[s + 3] * kv.w;
                a1[0] += w1[s + 0] * kv.x;  a1[1] += w1[s + 1] * kv.y;
                a1[2] += w1[s + 2] * kv.z;  a1[3] += w1[s + 3] * kv.w;
                a2[0] += w2[s + 0] * kv.x;  a2[1] += w2[s + 1] * kv.y;
                a2[2] += w2[s + 2] * kv.z;  a2[3] += w2[s + 3] * kv.w;
            }
            p0 = h0; p1 = h1; p2 = h2;
        }
    }

    const float inv = 1.0f / (float)K2;
    float* ob = out + (size_t)b * 3 * HW + (size_t)(i0 + ir) * WID + jj;
    float4 o0 = make_float4(a0[0]*inv, a0[1]*inv, a0[2]*inv, a0[3]*inv);
    float4 o1 = make_float4(a1[0]*inv, a1[1]*inv, a1[2]*inv, a1[3]*inv);
    float4 o2 = make_float4(a2[0]*inv, a2[1]*inv, a2[2]*inv, a2[3]*inv);
    *(float4*)(ob + 0 * HW) = o0;
    *(float4*)(ob + 1 * HW) = o1;
    *(float4*)(ob + 2 * HW) = o2;
}

extern "C" void kernel_launch(void* const* d_in, const int* in_sizes, int n_in,
                              void* d_out, int out_size)
{
    const float* x    = (const float*)d_in[0];
    const float* kern = (const float*)d_in[1];
    // defensive: identify tensors by size (input = 393216, kernel = 47316992)
    if (n_in >= 2 && in_sizes[0] > in_sizes[1]) {
        const float* t = x; x = kern; kern = t;
    }

    cudaFuncSetAttribute(svblur_kernel,
                         cudaFuncAttributeMaxDynamicSharedMemorySize, SMEM_BYTES);

    dim3 grid(HGT / TI, 2);   // (128, 2) = 256 blocks, 4 warps each
    svblur_kernel<<<grid, NTHR, SMEM_BYTES>>>(x, kern, (float*)d_out);
}